// round 4
// baseline (speedup 1.0000x reference)
#include <cuda_runtime.h>
#include <cuda_bf16.h>
#include <math.h>
#include <stdint.h>

#define NB 2
#define NN 256
#define NC 5
#define NHID 32
#define NFF 20

// Scratch (device globals: no allocation allowed)
__device__ float    g_part[NB*NN*NC];   // per-row x+f0 partials (plain stores)
__device__ unsigned g_ticket = 0;       // last-block-done; reset each launch

__device__ __forceinline__ float tanh_fast(float x){
    return 1.0f - 2.0f/(__expf(2.0f*x) + 1.0f);
}
__device__ __forceinline__ float gelu_t(float x){
    float x3 = x*x*x;
    float t = tanh_fast(0.7978845608028654f*(x + 0.044715f*x3));
    return 0.5f*x*(1.0f+t);
}
__device__ __forceinline__ float wredsum(float v){
    #pragma unroll
    for (int o=16;o;o>>=1) v += __shfl_xor_sync(0xffffffffu, v, o);
    return v;
}
__device__ __forceinline__ float wredmax(float v){
    #pragma unroll
    for (int o=16;o;o>>=1) v = fmaxf(v, __shfl_xor_sync(0xffffffffu, v, o));
    return v;
}
__device__ __forceinline__ bool adjval(const void* a, int mode, long idx){
    if (mode == 1) return ((const int*)a)[idx] != 0;
    if (mode == 2) return ((const float*)a)[idx] != 0.f;
    return ((const unsigned char*)a)[idx] != 0;
}

// ---------------------------------------------------------------------------
// ONE kernel: one block per (b,i) row; last finishing block runs the head MLP.
__global__ void __launch_bounds__(256)
attn_fused(const float* __restrict__ feats, const float* __restrict__ coors,
           const void*  __restrict__ adj,
           const float* __restrict__ Wq,  const float* __restrict__ Mk,
           const float* __restrict__ Mv,
           const float* __restrict__ R1,  const float* __restrict__ rb1,
           const float* __restrict__ R2,  const float* __restrict__ rb2,
           const float* __restrict__ Wo0,
           const float* __restrict__ gnA, const float* __restrict__ bnA,
           const float* __restrict__ gnF, const float* __restrict__ bnF,
           const float* __restrict__ Wf1, const float* __restrict__ Wf2,
           const float* __restrict__ Wh1, const float* __restrict__ bh1,
           const float* __restrict__ Wh2, const float* __restrict__ bh2,
           float* __restrict__ out){
    __shared__ float shR2k[1024], shR2v[1024];               // (32 t) x (32 hd)
    __shared__ float shWq[160], shMk[160], shMv[160];        // (5 c) x (32 hd)
    __shared__ float shR1[32], shrb1[32], shrb2k[32], shrb2v[32], shq[32];
    __shared__ unsigned shlanes[8];
    __shared__ int shmodev;
    __shared__ int shdcnt[8], shwcnt[8];
    __shared__ unsigned char shdir[256], shlist[256];
    __shared__ float shred[8][5];
    __shared__ float shmax[4], shsum[4];
    __shared__ float shpart[8][32];
    __shared__ float sho[32];
    __shared__ float shx[5];
    __shared__ unsigned sh_is_last;
    __shared__ float sp[NB][NC];
    __shared__ float shh[NB][128];

    int row = blockIdx.x;
    int b = row >> 8, i = row & 255;
    int tid = threadIdx.x;
    int lane = tid & 31, wp = tid >> 5;

    // ---- stage weights to smem + dtype detection (first 16KB of adj) ----
    for (int s=tid; s<1024; s+=256){
        int t = s >> 5, hd = s & 31;
        shR2k[s] = R2[t*384 + hd];
        shR2v[s] = R2[t*384 + 192 + hd];
    }
    if (tid < 160){
        shWq[tid] = Wq[tid]; shMk[tid] = Mk[tid]; shMv[tid] = Mv[tid];
    }
    if (tid < 32){
        shR1[tid]=R1[tid]; shrb1[tid]=rb1[tid];
        shrb2k[tid]=rb2[tid]; shrb2v[tid]=rb2[192+tid];
    }
    {
        unsigned m = 0;
        const uint32_t* aw = (const uint32_t*)adj;
        #pragma unroll
        for (int o=0;o<16;o++){
            uint32_t w = aw[tid*16 + o];
            m |= (w & 0x000000FFu ? 1u:0u) | (w & 0x0000FF00u ? 2u:0u)
               | (w & 0x00FF0000u ? 4u:0u) | (w & 0xFF000000u ? 8u:0u);
        }
        #pragma unroll
        for (int off=16; off; off>>=1) m |= __shfl_xor_sync(0xffffffffu, m, off);
        if (lane == 0) shlanes[wp] = m;
    }
    __syncthreads();
    if (tid == 0){
        unsigned lm = 0;
        #pragma unroll
        for (int w=0; w<8; w++) lm |= shlanes[w];
        int mode;
        if ((lm & 0xEu) == 0)      mode = 1;  // int32
        else if ((lm & 0x3u) == 0) mode = 2;  // float32
        else                       mode = 0;  // uint8
        shmodev = mode;
    }
    // q0 for row i (threads 0..31; each recomputes node-i norm)
    if (tid < 32){
        float xv[NC], n0[NC], mu = 0.f;
        #pragma unroll
        for (int c=0;c<NC;c++){ xv[c]=feats[row*NC+c]; n0[c]=fabsf(xv[c]); mu += n0[c]; }
        mu *= 0.2f;
        float var = 0.f;
        #pragma unroll
        for (int c=0;c<NC;c++){ float d=n0[c]-mu; var = fmaf(d,d,var); }
        var *= 0.2f;
        float sd = sqrtf(var) + 1e-8f;
        float q = 0.f;
        #pragma unroll
        for (int c=0;c<NC;c++){
            float ln = (n0[c]-mu)/sd * gnA[c] + bnA[c];
            float g = gelu_t(ln);
            float y = (xv[c] > 0.f) ? g : ((xv[c] < 0.f) ? -g : 0.f);
            q = fmaf(y, shWq[c*32+tid], q);
        }
        shq[tid] = q;
    }
    __syncthreads();
    int mode = shmodev;

    // ---- adjacency: direct row + 2-hop OR of neighbors' raw rows ----
    bool okd = adjval(adj, mode, (long)row*NN + tid);
    unsigned bald = __ballot_sync(0xffffffffu, okd);
    if (lane == 0) shdcnt[wp] = __popc(bald);
    __syncthreads();
    int based = 0, Mdir = 0;
    #pragma unroll
    for (int w=0; w<8; w++){ if (w < wp) based += shdcnt[w]; Mdir += shdcnt[w]; }
    if (okd) shdir[based + __popc(bald & ((1u<<lane)-1u))] = (unsigned char)tid;
    __syncthreads();

    bool col2 = false;
    for (int d=0; d<Mdir; d++){
        int j = shdir[d];
        col2 |= adjval(adj, mode, ((long)(b*NN + j))*NN + tid);
    }
    bool ok = okd | col2 | (tid == i);

    // deterministic compaction of active j's
    unsigned bal = __ballot_sync(0xffffffffu, ok);
    if (lane == 0) shwcnt[wp] = __popc(bal);
    __syncthreads();
    int base = 0, M = 0;
    #pragma unroll
    for (int w=0; w<8; w++){ if (w < wp) base += shwcnt[w]; M += shwcnt[w]; }
    if (ok) shlist[base + __popc(bal & ((1u<<lane)-1u))] = (unsigned char)tid;
    __syncthreads();

    bool act = tid < M;
    int j = act ? (int)shlist[tid] : 0;

    float lg[4] = {-1e9f,-1e9f,-1e9f,-1e9f};
    float k0[32], v0[32], y[NC];

    float cx = coors[row*3+0], cy = coors[row*3+1], cz = coors[row*3+2];

    if (act){
        int jr = (b << 8) + j;
        // neighbor node features: norm_se3 scalar path (recomputed inline)
        {
            float xv[NC], n0[NC], mu = 0.f;
            #pragma unroll
            for (int c=0;c<NC;c++){ xv[c]=feats[jr*NC+c]; n0[c]=fabsf(xv[c]); mu += n0[c]; }
            mu *= 0.2f;
            float var = 0.f;
            #pragma unroll
            for (int c=0;c<NC;c++){ float d=n0[c]-mu; var = fmaf(d,d,var); }
            var *= 0.2f;
            float sd = sqrtf(var) + 1e-8f;
            #pragma unroll
            for (int c=0;c<NC;c++){
                float ln = (n0[c]-mu)/sd * gnA[c] + bnA[c];
                float g = gelu_t(ln);
                y[c] = (xv[c] > 0.f) ? g : ((xv[c] < 0.f) ? -g : 0.f);
            }
        }
        float dx = cx - coors[jr*3+0];
        float dy = cy - coors[jr*3+1];
        float dz = cz - coors[jr*3+2];
        float dist = sqrtf(fmaf(dx,dx,fmaf(dy,dy,fmaf(dz,dz,1e-12f))));
        #pragma unroll
        for (int hd=0; hd<32; hd++){ k0[hd]=shrb2k[hd]; v0[hd]=shrb2v[hd]; }
        #pragma unroll 4
        for (int t=0; t<32; t++){
            float h = fmaxf(fmaf(dist, shR1[t], shrb1[t]), 0.f);
            const float4* wk = (const float4*)&shR2k[t*32];
            const float4* wv = (const float4*)&shR2v[t*32];
            #pragma unroll
            for (int c=0; c<8; c++){
                float4 a = wk[c];
                k0[4*c+0]=fmaf(h,a.x,k0[4*c+0]); k0[4*c+1]=fmaf(h,a.y,k0[4*c+1]);
                k0[4*c+2]=fmaf(h,a.z,k0[4*c+2]); k0[4*c+3]=fmaf(h,a.w,k0[4*c+3]);
                float4 bb = wv[c];
                v0[4*c+0]=fmaf(h,bb.x,v0[4*c+0]); v0[4*c+1]=fmaf(h,bb.y,v0[4*c+1]);
                v0[4*c+2]=fmaf(h,bb.z,v0[4*c+2]); v0[4*c+3]=fmaf(h,bb.w,v0[4*c+3]);
            }
        }
        float l[4] = {0.f,0.f,0.f,0.f};
        #pragma unroll
        for (int hd=0; hd<32; hd++){
            float yk = 0.f;
            #pragma unroll
            for (int c=0;c<NC;c++) yk = fmaf(y[c], shMk[c*32+hd], yk);
            l[hd>>3] = fmaf(shq[hd]*yk, k0[hd], l[hd>>3]);
        }
        #pragma unroll
        for (int h=0; h<4; h++) lg[h] = l[h]*0.35355339059327373f;  // 1/sqrt(8)
    }

    // ---- masked softmax over active j's (per head) ----
    float m4[4];
    #pragma unroll
    for (int h=0; h<4; h++) m4[h] = wredmax(lg[h]);
    if (lane == 0){
        #pragma unroll
        for (int h=0; h<4; h++) shred[wp][h] = m4[h];
    }
    __syncthreads();
    if (tid < 4){
        float mm = -1e9f;
        #pragma unroll
        for (int w=0; w<8; w++) mm = fmaxf(mm, shred[w][tid]);
        shmax[tid] = mm;
    }
    __syncthreads();
    float e[4];
    #pragma unroll
    for (int h=0; h<4; h++) e[h] = act ? __expf(lg[h]-shmax[h]) : 0.f;
    float s4[4];
    #pragma unroll
    for (int h=0; h<4; h++) s4[h] = wredsum(e[h]);
    if (lane == 0){
        #pragma unroll
        for (int h=0; h<4; h++) shred[wp][h] = s4[h];
    }
    __syncthreads();
    if (tid < 4){
        float ss = 0.f;
        #pragma unroll
        for (int w=0; w<8; w++) ss += shred[w][tid];
        shsum[tid] = ss;
    }
    __syncthreads();
    float a4[4];
    #pragma unroll
    for (int h=0; h<4; h++) a4[h] = e[h]/shsum[h];

    // ---- o0[hd] = sum_j attn * v0*yv ----
    #pragma unroll
    for (int hd=0; hd<32; hd++){
        float o = 0.f;
        if (act){
            float yv = 0.f;
            #pragma unroll
            for (int c=0;c<NC;c++) yv = fmaf(y[c], shMv[c*32+hd], yv);
            o = a4[hd>>3]*v0[hd]*yv;
        }
        o = wredsum(o);
        if (lane == 0) shpart[wp][hd] = o;
    }
    __syncthreads();
    if (tid < 32){
        float o = 0.f;
        #pragma unroll
        for (int w=0; w<8; w++) o += shpart[w][tid];
        sho[tid] = o;
    }
    __syncthreads();
    if (tid < 5){
        float d = 0.f;
        #pragma unroll
        for (int hd=0; hd<32; hd++) d = fmaf(sho[hd], Wo0[hd*NC+tid], d);
        shx[tid] = feats[row*NC+tid] + d;     // residual on ORIGINAL x0
    }
    __syncthreads();
    // ---- FF epilogue for this row -> partial store ----
    if (tid == 0){
        float x[5], n0[5], mu = 0.f;
        #pragma unroll
        for (int c=0;c<5;c++){ x[c]=shx[c]; n0[c]=fabsf(x[c]); mu+=n0[c]; }
        mu *= 0.2f;
        float var = 0.f;
        #pragma unroll
        for (int c=0;c<5;c++){ float d=n0[c]-mu; var=fmaf(d,d,var); }
        var *= 0.2f;
        float sd = sqrtf(var)+1e-8f;
        float yv[5];
        #pragma unroll
        for (int c=0;c<5;c++){
            float ln = (n0[c]-mu)/sd*gnF[c]+bnF[c];
            float g = gelu_t(ln);
            yv[c] = (x[c]>0.f)? g : ((x[c]<0.f)? -g : 0.f);
        }
        float f0[5] = {0.f,0.f,0.f,0.f,0.f};
        #pragma unroll 4
        for (int f=0; f<NFF; f++){
            float hsum = 0.f;
            #pragma unroll
            for (int c=0;c<5;c++) hsum = fmaf(yv[c], Wf1[c*NFF+f], hsum);
            float hg = gelu_t(hsum);
            #pragma unroll
            for (int c=0;c<5;c++) f0[c] = fmaf(hg, Wf2[f*NC+c], f0[c]);
        }
        #pragma unroll
        for (int c=0;c<5;c++) g_part[row*NC+c] = x[c]+f0[c];
    }

    // ---- last-block-done: head MLP ----
    __threadfence();
    __syncthreads();
    if (tid == 0) sh_is_last = (atomicAdd(&g_ticket, 1u) == (unsigned)(gridDim.x - 1));
    __syncthreads();
    if (!sh_is_last) return;

    // pooled[b][c] = sum over 256 rows (deterministic tree order)
    #pragma unroll
    for (int bb=0; bb<NB; bb++){
        float v[5];
        const float* pr = g_part + (bb*256 + tid)*NC;
        #pragma unroll
        for (int c=0;c<5;c++) v[c] = pr[c];
        #pragma unroll
        for (int c=0;c<5;c++){
            float r = wredsum(v[c]);
            if (lane == 0) shred[wp][c] = r;
        }
        __syncthreads();
        if (tid < 5){
            float ss = 0.f;
            #pragma unroll
            for (int w=0; w<8; w++) ss += shred[w][tid];
            sp[bb][tid] = ss * (1.0f/(float)NN);
        }
        __syncthreads();
    }
    // hidden layer: 256 threads = 2 batches x 128 units
    {
        int bb = tid >> 7, u = tid & 127;
        float sv = bh1[u];
        #pragma unroll
        for (int c=0;c<NC;c++) sv = fmaf(sp[bb][c], Wh1[c*128+u], sv);
        shh[bb][u] = fmaxf(sv, 0.f);
    }
    __syncthreads();
    // outputs: 18 values; warp wp handles o = wp, wp+8, wp+16
    for (int o = wp; o < NB*9; o += 8){
        int bb = o/9, oo = o%9;
        float sv = 0.f;
        for (int f = lane; f < 128; f += 32)
            sv = fmaf(shh[bb][f], Wh2[f*9+oo], sv);
        sv = wredsum(sv);
        if (lane == 0) out[o] = bh2[oo] + sv;
    }
    if (tid == 0) atomicExch(&g_ticket, 0u);   // replay-safe reset
}

// ---------------------------------------------------------------------------
extern "C" void kernel_launch(void* const* d_in, const int* in_sizes, int n_in,
                              void* d_out, int out_size){
    const float* feats = (const float*)d_in[0];
    const float* coors = (const float*)d_in[1];
    const void*  adj   = d_in[2];
    const float* Wq  = (const float*)d_in[3];
    const float* Mk  = (const float*)d_in[4];
    const float* Mv  = (const float*)d_in[5];
    const float* R1  = (const float*)d_in[6];
    const float* rb1 = (const float*)d_in[7];
    const float* R2  = (const float*)d_in[8];
    const float* rb2 = (const float*)d_in[9];
    const float* Wo0 = (const float*)d_in[10];
    // d_in[11] Wo1 unused (vector channel dead for scalar output)
    const float* gnA = (const float*)d_in[12];
    const float* bnA = (const float*)d_in[13];
    const float* gnF = (const float*)d_in[14];
    const float* bnF = (const float*)d_in[15];
    const float* Wf1 = (const float*)d_in[16];
    const float* Wf2 = (const float*)d_in[17];
    // d_in[18] gs, d_in[19] bs unused (vector FF path dead)
    const float* Wh1 = (const float*)d_in[20];
    const float* bh1 = (const float*)d_in[21];
    const float* Wh2 = (const float*)d_in[22];
    const float* bh2 = (const float*)d_in[23];
    float* out = (float*)d_out;

    attn_fused<<<NB*NN, 256>>>(feats, coors, adj, Wq, Mk, Mv,
                               R1, rb1, R2, rb2, Wo0,
                               gnA, bnA, gnF, bnF, Wf1, Wf2,
                               Wh1, bh1, Wh2, bh2, out);
}

// round 5
// speedup vs baseline: 1.8120x; 1.8120x over previous
#include <cuda_runtime.h>
#include <cuda_bf16.h>
#include <math.h>
#include <stdint.h>

#define NB 2
#define NN 256
#define NC 5
#define NHID 32
#define NFF 20

// Scratch (device globals: no allocation allowed)
__device__ float    g_part[NB*NN*NC];   // per-row x+f0 partials (plain stores)
__device__ unsigned g_ticket = 0;       // last-block-done; reset each launch

__device__ __forceinline__ float tanh_fast(float x){
    return 1.0f - 2.0f/(__expf(2.0f*x) + 1.0f);
}
__device__ __forceinline__ float gelu_t(float x){
    float x3 = x*x*x;
    float t = tanh_fast(0.7978845608028654f*(x + 0.044715f*x3));
    return 0.5f*x*(1.0f+t);
}
__device__ __forceinline__ float wredsum(float v){
    #pragma unroll
    for (int o=16;o;o>>=1) v += __shfl_xor_sync(0xffffffffu, v, o);
    return v;
}
__device__ __forceinline__ float wredmax(float v){
    #pragma unroll
    for (int o=16;o;o>>=1) v = fmaxf(v, __shfl_xor_sync(0xffffffffu, v, o));
    return v;
}
__device__ __forceinline__ bool adjval(const void* a, int mode, long idx){
    if (mode == 1) return ((const int*)a)[idx] != 0;
    if (mode == 2) return ((const float*)a)[idx] != 0.f;
    return ((const unsigned char*)a)[idx] != 0;
}

// ---------------------------------------------------------------------------
// ONE kernel: one block per (b,i) row; last finishing block runs the head MLP.
// Interior parallelization: tid = edge_slot*4 + head.
__global__ void __launch_bounds__(256,4)
attn_fused(const float* __restrict__ feats, const float* __restrict__ coors,
           const void*  __restrict__ adj,
           const float* __restrict__ Wq,  const float* __restrict__ Mk,
           const float* __restrict__ Mv,
           const float* __restrict__ R1,  const float* __restrict__ rb1,
           const float* __restrict__ R2,  const float* __restrict__ rb2,
           const float* __restrict__ Wo0,
           const float* __restrict__ gnA, const float* __restrict__ bnA,
           const float* __restrict__ gnF, const float* __restrict__ bnF,
           const float* __restrict__ Wf1, const float* __restrict__ Wf2,
           const float* __restrict__ Wh1, const float* __restrict__ bh1,
           const float* __restrict__ Wh2, const float* __restrict__ bh2,
           float* __restrict__ out){
    __shared__ float shR2k[1024], shR2v[1024];               // (32 t) x (32 hd)
    __shared__ float shWq[160], shMk[160], shMv[160];        // (5 c) x (32 hd)
    __shared__ float shR1[32], shrb1[32], shrb2k[32], shrb2v[32], shq[32];
    __shared__ unsigned shlanes[8];
    __shared__ int shmodev;
    __shared__ unsigned shadjm[8];
    __shared__ int shcnt[8];
    __shared__ unsigned char shdir[256], shlist[256];
    __shared__ float shdist[256], shy[256*5];
    __shared__ float shlog[4*256];                           // logits -> exp
    __shared__ float shred[8][5];
    __shared__ float shmax[4], shsum[4];
    __shared__ float shoacc[8][32];
    __shared__ float sho[32], shx[5];
    __shared__ unsigned sh_is_last;
    __shared__ float sp[NB][NC];
    __shared__ float shh[NB][128];

    int row = blockIdx.x;
    int b = row >> 8, i = row & 255;
    int tid = threadIdx.x;
    int lane = tid & 31, wp = tid >> 5;

    // ---- stage weights + dtype detection (first 8KB of adj) ----
    for (int s=tid; s<1024; s+=256){
        int t = s >> 5, hd = s & 31;
        shR2k[s] = R2[t*384 + hd];
        shR2v[s] = R2[t*384 + 192 + hd];
    }
    if (tid < 160){
        shWq[tid] = Wq[tid]; shMk[tid] = Mk[tid]; shMv[tid] = Mv[tid];
    }
    if (tid < 32){
        shR1[tid]=R1[tid]; shrb1[tid]=rb1[tid];
        shrb2k[tid]=rb2[tid]; shrb2v[tid]=rb2[192+tid];
    }
    if (tid < 8) shadjm[tid] = (tid == (i>>5)) ? (1u << (i&31)) : 0u;  // eye
    {
        unsigned m = 0;
        const uint32_t* aw = (const uint32_t*)adj;
        #pragma unroll
        for (int o=0;o<8;o++){
            uint32_t w = aw[tid*8 + o];
            m |= (w & 0x000000FFu ? 1u:0u) | (w & 0x0000FF00u ? 2u:0u)
               | (w & 0x00FF0000u ? 4u:0u) | (w & 0xFF000000u ? 8u:0u);
        }
        #pragma unroll
        for (int off=16; off; off>>=1) m |= __shfl_xor_sync(0xffffffffu, m, off);
        if (lane == 0) shlanes[wp] = m;
    }
    __syncthreads();
    if (tid == 0){
        unsigned lm = 0;
        #pragma unroll
        for (int w=0; w<8; w++) lm |= shlanes[w];
        shmodev = ((lm & 0xEu) == 0) ? 1 : (((lm & 0x3u) == 0) ? 2 : 0);
    }
    // q0 for row i (threads 0..31)
    if (tid < 32){
        float xv[NC], n0[NC], mu = 0.f;
        #pragma unroll
        for (int c=0;c<NC;c++){ xv[c]=feats[row*NC+c]; n0[c]=fabsf(xv[c]); mu += n0[c]; }
        mu *= 0.2f;
        float var = 0.f;
        #pragma unroll
        for (int c=0;c<NC;c++){ float d=n0[c]-mu; var = fmaf(d,d,var); }
        var *= 0.2f;
        float sd = sqrtf(var) + 1e-8f;
        float q = 0.f;
        #pragma unroll
        for (int c=0;c<NC;c++){
            float ln = (n0[c]-mu)/sd * gnA[c] + bnA[c];
            float g = gelu_t(ln);
            float y = (xv[c] > 0.f) ? g : ((xv[c] < 0.f) ? -g : 0.f);
            q = fmaf(y, shWq[c*32+tid], q);
        }
        shq[tid] = q;
    }
    __syncthreads();
    int mode = shmodev;

    // ---- adjacency: direct row -> dir list; 2-hop OR across warps ----
    bool okd = adjval(adj, mode, (long)row*NN + tid);
    unsigned bald = __ballot_sync(0xffffffffu, okd);
    if (lane == 0){ shcnt[wp] = __popc(bald); atomicOr(&shadjm[wp], bald); }
    __syncthreads();
    int based = 0, Mdir = 0;
    #pragma unroll
    for (int w=0; w<8; w++){ if (w < wp) based += shcnt[w]; Mdir += shcnt[w]; }
    if (okd) shdir[based + __popc(bald & ((1u<<lane)-1u))] = (unsigned char)tid;
    __syncthreads();

    for (int d = wp; d < Mdir; d += 8){
        long jbase = ((long)(b*NN + shdir[d]))*NN;
        #pragma unroll
        for (int g=0; g<8; g++){
            bool v = adjval(adj, mode, jbase + g*32 + lane);
            unsigned bb = __ballot_sync(0xffffffffu, v);
            if (lane == 0 && bb) atomicOr(&shadjm[g], bb);
        }
    }
    __syncthreads();

    // compaction of active j's (ascending)
    bool ok = (shadjm[tid>>5] >> (tid&31)) & 1u;
    unsigned bal = __ballot_sync(0xffffffffu, ok);
    if (lane == 0) shcnt[wp] = __popc(bal);
    __syncthreads();
    int base = 0, M = 0;
    #pragma unroll
    for (int w=0; w<8; w++){ if (w < wp) base += shcnt[w]; M += shcnt[w]; }
    if (ok) shlist[base + __popc(bal & ((1u<<lane)-1u))] = (unsigned char)tid;
    __syncthreads();

    // ---- phase 0: per-edge dist + normalized features y[5] ----
    float cx = coors[row*3+0], cy = coors[row*3+1], cz = coors[row*3+2];
    for (int e = tid; e < M; e += 256){
        int jr = (b << 8) + (int)shlist[e];
        float dx = cx - coors[jr*3+0];
        float dy = cy - coors[jr*3+1];
        float dz = cz - coors[jr*3+2];
        shdist[e] = sqrtf(fmaf(dx,dx,fmaf(dy,dy,fmaf(dz,dz,1e-12f))));
        float xv[NC], n0[NC], mu = 0.f;
        #pragma unroll
        for (int c=0;c<NC;c++){ xv[c]=feats[jr*NC+c]; n0[c]=fabsf(xv[c]); mu += n0[c]; }
        mu *= 0.2f;
        float var = 0.f;
        #pragma unroll
        for (int c=0;c<NC;c++){ float d=n0[c]-mu; var = fmaf(d,d,var); }
        var *= 0.2f;
        float sd = sqrtf(var) + 1e-8f;
        #pragma unroll
        for (int c=0;c<NC;c++){
            float ln = (n0[c]-mu)/sd * gnA[c] + bnA[c];
            float g = gelu_t(ln);
            shy[e*5+c] = (xv[c] > 0.f) ? g : ((xv[c] < 0.f) ? -g : 0.f);
        }
    }
    __syncthreads();

    // ---- phase 1: logits.  thread = (edge slot e, head h) ----
    int h = tid & 3;
    int eloc = tid >> 2;
    for (int et = 0; et < M; et += 64){
        int e = et + eloc;
        if (e < M){
            float dist = shdist[e];
            float k0[8];
            #pragma unroll
            for (int d=0; d<8; d++) k0[d] = shrb2k[h*8+d];
            #pragma unroll 8
            for (int t=0; t<32; t++){
                float hv = fmaxf(fmaf(dist, shR1[t], shrb1[t]), 0.f);
                const float4* wk = (const float4*)&shR2k[t*32 + h*8];
                float4 a0 = wk[0], a1 = wk[1];
                k0[0]=fmaf(hv,a0.x,k0[0]); k0[1]=fmaf(hv,a0.y,k0[1]);
                k0[2]=fmaf(hv,a0.z,k0[2]); k0[3]=fmaf(hv,a0.w,k0[3]);
                k0[4]=fmaf(hv,a1.x,k0[4]); k0[5]=fmaf(hv,a1.y,k0[5]);
                k0[6]=fmaf(hv,a1.z,k0[6]); k0[7]=fmaf(hv,a1.w,k0[7]);
            }
            float l = 0.f;
            #pragma unroll
            for (int d=0; d<8; d++){
                float yk = 0.f;
                #pragma unroll
                for (int c=0;c<NC;c++) yk = fmaf(shy[e*5+c], shMk[c*32+h*8+d], yk);
                l = fmaf(shq[h*8+d]*yk, k0[d], l);
            }
            shlog[h*256+e] = l*0.35355339059327373f;  // 1/sqrt(8)
        }
    }
    __syncthreads();

    // ---- phase 2: block softmax over edges, per head (thread = edge) ----
    {
        float lv[4];
        #pragma unroll
        for (int hh=0; hh<4; hh++) lv[hh] = (tid < M) ? shlog[hh*256+tid] : -1e9f;
        #pragma unroll
        for (int hh=0; hh<4; hh++){
            float mm = wredmax(lv[hh]);
            if (lane == 0) shred[wp][hh] = mm;
        }
        __syncthreads();
        if (tid < 4){
            float mm = -1e9f;
            #pragma unroll
            for (int w=0; w<8; w++) mm = fmaxf(mm, shred[w][tid]);
            shmax[tid] = mm;
        }
        __syncthreads();
        float ex[4];
        #pragma unroll
        for (int hh=0; hh<4; hh++) ex[hh] = (tid < M) ? __expf(lv[hh]-shmax[hh]) : 0.f;
        if (tid < M){
            #pragma unroll
            for (int hh=0; hh<4; hh++) shlog[hh*256+tid] = ex[hh];
        }
        #pragma unroll
        for (int hh=0; hh<4; hh++){
            float ss = wredsum(ex[hh]);
            if (lane == 0) shred[wp][hh] = ss;
        }
        __syncthreads();
        if (tid < 4){
            float ss = 0.f;
            #pragma unroll
            for (int w=0; w<8; w++) ss += shred[w][tid];
            shsum[tid] = ss;
        }
        __syncthreads();
    }

    // ---- phase 3: o0 accumulation (thread = (e,h), v-slice recompute) ----
    float acc[8];
    #pragma unroll
    for (int d=0; d<8; d++) acc[d] = 0.f;
    float inv_s = 1.0f/shsum[h];
    for (int et = 0; et < M; et += 64){
        int e = et + eloc;
        if (e < M){
            float attn = shlog[h*256+e]*inv_s;
            float dist = shdist[e];
            float v0[8];
            #pragma unroll
            for (int d=0; d<8; d++) v0[d] = shrb2v[h*8+d];
            #pragma unroll 8
            for (int t=0; t<32; t++){
                float hv = fmaxf(fmaf(dist, shR1[t], shrb1[t]), 0.f);
                const float4* wv = (const float4*)&shR2v[t*32 + h*8];
                float4 a0 = wv[0], a1 = wv[1];
                v0[0]=fmaf(hv,a0.x,v0[0]); v0[1]=fmaf(hv,a0.y,v0[1]);
                v0[2]=fmaf(hv,a0.z,v0[2]); v0[3]=fmaf(hv,a0.w,v0[3]);
                v0[4]=fmaf(hv,a1.x,v0[4]); v0[5]=fmaf(hv,a1.y,v0[5]);
                v0[6]=fmaf(hv,a1.z,v0[6]); v0[7]=fmaf(hv,a1.w,v0[7]);
            }
            #pragma unroll
            for (int d=0; d<8; d++){
                float yv = 0.f;
                #pragma unroll
                for (int c=0;c<NC;c++) yv = fmaf(shy[e*5+c], shMv[c*32+h*8+d], yv);
                acc[d] = fmaf(attn*v0[d], yv, acc[d]);
            }
        }
    }
    // reduce over the 8 edge slots within each warp (strides 4,8,16 toggle e bits)
    #pragma unroll
    for (int d=0; d<8; d++){
        #pragma unroll
        for (int o=4; o<32; o<<=1) acc[d] += __shfl_xor_sync(0xffffffffu, acc[d], o);
    }
    if (lane < 4){
        #pragma unroll
        for (int d=0; d<8; d++) shoacc[wp][lane*8+d] = acc[d];
    }
    __syncthreads();
    if (tid < 32){
        float o = 0.f;
        #pragma unroll
        for (int w=0; w<8; w++) o += shoacc[w][tid];
        sho[tid] = o;
    }
    __syncthreads();
    if (tid < 5){
        float d = 0.f;
        #pragma unroll
        for (int hd=0; hd<32; hd++) d = fmaf(sho[hd], Wo0[hd*NC+tid], d);
        shx[tid] = feats[row*NC+tid] + d;     // residual on ORIGINAL x0
    }
    __syncthreads();
    // ---- FF epilogue for this row -> partial store ----
    if (tid == 0){
        float x[5], n0[5], mu = 0.f;
        #pragma unroll
        for (int c=0;c<5;c++){ x[c]=shx[c]; n0[c]=fabsf(x[c]); mu+=n0[c]; }
        mu *= 0.2f;
        float var = 0.f;
        #pragma unroll
        for (int c=0;c<5;c++){ float d=n0[c]-mu; var=fmaf(d,d,var); }
        var *= 0.2f;
        float sd = sqrtf(var)+1e-8f;
        float yv[5];
        #pragma unroll
        for (int c=0;c<5;c++){
            float ln = (n0[c]-mu)/sd*gnF[c]+bnF[c];
            float g = gelu_t(ln);
            yv[c] = (x[c]>0.f)? g : ((x[c]<0.f)? -g : 0.f);
        }
        float f0[5] = {0.f,0.f,0.f,0.f,0.f};
        #pragma unroll 4
        for (int f=0; f<NFF; f++){
            float hsum = 0.f;
            #pragma unroll
            for (int c=0;c<5;c++) hsum = fmaf(yv[c], Wf1[c*NFF+f], hsum);
            float hg = gelu_t(hsum);
            #pragma unroll
            for (int c=0;c<5;c++) f0[c] = fmaf(hg, Wf2[f*NC+c], f0[c]);
        }
        #pragma unroll
        for (int c=0;c<5;c++) g_part[row*NC+c] = x[c]+f0[c];
    }

    // ---- last-block-done: head MLP ----
    __threadfence();
    __syncthreads();
    if (tid == 0) sh_is_last = (atomicAdd(&g_ticket, 1u) == (unsigned)(gridDim.x - 1));
    __syncthreads();
    if (!sh_is_last) return;

    #pragma unroll
    for (int bb=0; bb<NB; bb++){
        float v[5];
        const float* pr = g_part + (bb*256 + tid)*NC;
        #pragma unroll
        for (int c=0;c<5;c++) v[c] = pr[c];
        #pragma unroll
        for (int c=0;c<5;c++){
            float r = wredsum(v[c]);
            if (lane == 0) shred[wp][c] = r;
        }
        __syncthreads();
        if (tid < 5){
            float ss = 0.f;
            #pragma unroll
            for (int w=0; w<8; w++) ss += shred[w][tid];
            sp[bb][tid] = ss * (1.0f/(float)NN);
        }
        __syncthreads();
    }
    {
        int bb = tid >> 7, u = tid & 127;
        float sv = bh1[u];
        #pragma unroll
        for (int c=0;c<NC;c++) sv = fmaf(sp[bb][c], Wh1[c*128+u], sv);
        shh[bb][u] = fmaxf(sv, 0.f);
    }
    __syncthreads();
    for (int o = wp; o < NB*9; o += 8){
        int bb = o/9, oo = o%9;
        float sv = 0.f;
        for (int f = lane; f < 128; f += 32)
            sv = fmaf(shh[bb][f], Wh2[f*9+oo], sv);
        sv = wredsum(sv);
        if (lane == 0) out[o] = bh2[oo] + sv;
    }
    if (tid == 0) atomicExch(&g_ticket, 0u);   // replay-safe reset
}

// ---------------------------------------------------------------------------
extern "C" void kernel_launch(void* const* d_in, const int* in_sizes, int n_in,
                              void* d_out, int out_size){
    const float* feats = (const float*)d_in[0];
    const float* coors = (const float*)d_in[1];
    const void*  adj   = d_in[2];
    const float* Wq  = (const float*)d_in[3];
    const float* Mk  = (const float*)d_in[4];
    const float* Mv  = (const float*)d_in[5];
    const float* R1  = (const float*)d_in[6];
    const float* rb1 = (const float*)d_in[7];
    const float* R2  = (const float*)d_in[8];
    const float* rb2 = (const float*)d_in[9];
    const float* Wo0 = (const float*)d_in[10];
    const float* gnA = (const float*)d_in[12];
    const float* bnA = (const float*)d_in[13];
    const float* gnF = (const float*)d_in[14];
    const float* bnF = (const float*)d_in[15];
    const float* Wf1 = (const float*)d_in[16];
    const float* Wf2 = (const float*)d_in[17];
    const float* Wh1 = (const float*)d_in[20];
    const float* bh1 = (const float*)d_in[21];
    const float* Wh2 = (const float*)d_in[22];
    const float* bh2 = (const float*)d_in[23];
    float* out = (float*)d_out;

    attn_fused<<<NB*NN, 256>>>(feats, coors, adj, Wq, Mk, Mv,
                               R1, rb1, R2, rb2, Wo0,
                               gnA, bnA, gnF, bnF, Wf1, Wf2,
                               Wh1, bh1, Wh2, bh2, out);
}